// round 11
// baseline (speedup 1.0000x reference)
#include <cuda_runtime.h>
#include <math.h>

#define EMB 128
#define BATCH 8192
#define NTHREADS 256
#define GRID_PERSIST (148 * 6)   // one full wave at occ=6

__device__ int g_seg_start[BATCH + 1];
__device__ float g_dwf[EMB];

// Coalesced boundary scan over sorted segment_ids + dwf precompute.
__global__ void bounds_scan_kernel(const int* __restrict__ seg, int T,
                                   const float* __restrict__ w,
                                   const float* __restrict__ fingerprint) {
    int i = blockIdx.x * blockDim.x + threadIdx.x;
    if (blockIdx.x == 0 && threadIdx.x < EMB)
        g_dwf[threadIdx.x] = w[threadIdx.x * EMB + threadIdx.x] * fingerprint[threadIdx.x];
    if (i >= T) return;
    const int s = seg[i];
    if (i == 0) {
        for (int b = 0; b <= s; b++) g_seg_start[b] = 0;
    } else {
        const int prev = seg[i - 1];
        for (int b = prev + 1; b <= s; b++) g_seg_start[b] = i;
    }
    if (i == T - 1) {
        for (int b = s + 1; b <= BATCH; b++) g_seg_start[b] = T;
    }
}

__global__ __launch_bounds__(NTHREADS, 6)
void fattn_kernel(const float* __restrict__ value,
                  const float* __restrict__ key,
                  float* __restrict__ out) {
    // Double-buffered per-warp partials (parity by segment index):
    // [2][8 warps][64 float4]; value cols idx 0..31, key cols idx 32..63.
    __shared__ float4 wsum[2][8][64];
    __shared__ float zred[2][8];

    const int tid  = threadIdx.x;
    const int wid  = tid >> 5;
    const int lane = tid & 31;

    const float4 d = *reinterpret_cast<const float4*>(g_dwf + lane * 4);
    const float inv_scale = 0.08838834764831845f; // 1/sqrt(128)

    int buf = 0;
    for (int b = blockIdx.x; b < BATCH; b += GRID_PERSIST, buf ^= 1) {
        const int start = g_seg_start[b];
        const int n     = g_seg_start[b + 1] - start;

        float4 accV = make_float4(0.f, 0.f, 0.f, 0.f);
        float4 accK = make_float4(0.f, 0.f, 0.f, 0.f);
        float z = 0.f;

        const float* kbase = key   + (long long)start * EMB + lane * 4;
        const float* vbase = value + (long long)start * EMB + lane * 4;

        int t = wid * 2;
        for (; t + 1 < n; t += 16) {
            const float4 k0 = *reinterpret_cast<const float4*>(kbase + (long long)t * EMB);
            const float4 k1 = *reinterpret_cast<const float4*>(kbase + (long long)(t + 1) * EMB);
            const float4 v0 = *reinterpret_cast<const float4*>(vbase + (long long)t * EMB);
            const float4 v1 = *reinterpret_cast<const float4*>(vbase + (long long)(t + 1) * EMB);

            float p0 = (k0.x * d.x + k0.y * d.y) + (k0.z * d.z + k0.w * d.w);
            float p1 = (k1.x * d.x + k1.y * d.y) + (k1.z * d.z + k1.w * d.w);
            #pragma unroll
            for (int o = 16; o > 0; o >>= 1) {
                p0 += __shfl_xor_sync(0xffffffffu, p0, o);
                p1 += __shfl_xor_sync(0xffffffffu, p1, o);
            }
            const float e0 = __expf(p0 * inv_scale);
            const float e1 = __expf(p1 * inv_scale);
            z += e0 + e1;
            accK.x += e0 * k0.x + e1 * k1.x;
            accK.y += e0 * k0.y + e1 * k1.y;
            accK.z += e0 * k0.z + e1 * k1.z;
            accK.w += e0 * k0.w + e1 * k1.w;
            accV.x += e0 * v0.x + e1 * v1.x;
            accV.y += e0 * v0.y + e1 * v1.y;
            accV.z += e0 * v0.z + e1 * v1.z;
            accV.w += e0 * v0.w + e1 * v1.w;
        }
        if (t < n) {  // tail token
            const float4 k0 = *reinterpret_cast<const float4*>(kbase + (long long)t * EMB);
            const float4 v0 = *reinterpret_cast<const float4*>(vbase + (long long)t * EMB);
            float p0 = (k0.x * d.x + k0.y * d.y) + (k0.z * d.z + k0.w * d.w);
            #pragma unroll
            for (int o = 16; o > 0; o >>= 1) p0 += __shfl_xor_sync(0xffffffffu, p0, o);
            const float e0 = __expf(p0 * inv_scale);
            z += e0;
            accK.x += e0 * k0.x; accK.y += e0 * k0.y;
            accK.z += e0 * k0.z; accK.w += e0 * k0.w;
            accV.x += e0 * v0.x; accV.y += e0 * v0.y;
            accV.z += e0 * v0.z; accV.w += e0 * v0.w;
        }

        wsum[buf][wid][lane]      = accV;
        wsum[buf][wid][32 + lane] = accK;
        if (lane == 0) zred[buf][wid] = z;
        __syncthreads();   // single barrier per segment (buffers alternate)

        float zz = (zred[buf][0] + zred[buf][1]) + (zred[buf][2] + zred[buf][3])
                 + (zred[buf][4] + zred[buf][5]) + (zred[buf][6] + zred[buf][7]);
        const float invZ = (zz > 0.f) ? (1.f / zz) : 0.f;

        const float* ws = reinterpret_cast<const float*>(wsum[buf]);  // [8][256]
        const float a0 = ws[0 * 256 + tid], a1 = ws[1 * 256 + tid];
        const float a2 = ws[2 * 256 + tid], a3 = ws[3 * 256 + tid];
        const float a4 = ws[4 * 256 + tid], a5 = ws[5 * 256 + tid];
        const float a6 = ws[6 * 256 + tid], a7 = ws[7 * 256 + tid];
        const float acc = ((a0 + a1) + (a2 + a3)) + ((a4 + a5) + (a6 + a7));
        out[(long long)b * (2 * EMB) + tid] = acc * invZ;
    }
}

extern "C" void kernel_launch(void* const* d_in, const int* in_sizes, int n_in,
                              void* d_out, int out_size) {
    const float* value = (const float*)d_in[0];
    const float* key   = (const float*)d_in[1];
    const int*   seg   = (const int*)d_in[2];
    const float* fp    = (const float*)d_in[3];
    const float* w     = (const float*)d_in[4];
    float* out = (float*)d_out;
    const int T = in_sizes[2];

    bounds_scan_kernel<<<(T + 255) / 256, 256>>>(seg, T, w, fp);
    fattn_kernel<<<GRID_PERSIST, NTHREADS>>>(value, key, out);
}

// round 12
// speedup vs baseline: 1.0968x; 1.0968x over previous
#include <cuda_runtime.h>
#include <math.h>

#define EMB 128
#define BATCH 8192
#define NTHREADS 256

__device__ int g_seg_start[BATCH + 1];

// Vectorized boundary scan: thread i covers tokens 4i..4i+3 via one int4 load.
__global__ void bounds_scan_kernel(const int* __restrict__ seg, int T) {
    const int i = blockIdx.x * blockDim.x + threadIdx.x;
    const int base = i * 4;
    if (base >= T) return;

    if (base + 3 < T) {
        const int4 s4 = *reinterpret_cast<const int4*>(seg + base);
        int prev;
        if (base == 0) {
            for (int b = 0; b <= s4.x; b++) g_seg_start[b] = 0;
            prev = s4.x;
        } else {
            prev = seg[base - 1];
            for (int b = prev + 1; b <= s4.x; b++) g_seg_start[b] = base;
            prev = s4.x;
        }
        for (int b = prev + 1; b <= s4.y; b++) g_seg_start[b] = base + 1;
        for (int b = s4.y + 1; b <= s4.z; b++) g_seg_start[b] = base + 2;
        for (int b = s4.z + 1; b <= s4.w; b++) g_seg_start[b] = base + 3;
        if (base + 4 == T) {
            for (int b = s4.w + 1; b <= BATCH; b++) g_seg_start[b] = T;
        }
    } else {
        // ragged tail (T not divisible by 4)
        for (int j = base; j < T; j++) {
            const int s = seg[j];
            if (j == 0) {
                for (int b = 0; b <= s; b++) g_seg_start[b] = 0;
            } else {
                const int prev = seg[j - 1];
                for (int b = prev + 1; b <= s; b++) g_seg_start[b] = j;
            }
            if (j == T - 1) {
                for (int b = s + 1; b <= BATCH; b++) g_seg_start[b] = T;
            }
        }
    }
}

__global__ __launch_bounds__(NTHREADS, 6)
void fattn_kernel(const float* __restrict__ value,
                  const float* __restrict__ key,
                  const float* __restrict__ fingerprint,
                  const float* __restrict__ w,
                  float* __restrict__ out) {
    // Per-warp partial sums: [8 warps][64 float4]; value cols idx 0..31,
    // key cols idx 32..63. 8 KB.
    __shared__ float4 wsum[8][64];
    __shared__ float zred[8];
    __shared__ float dwf[EMB];

    const int b    = blockIdx.x;
    const int tid  = threadIdx.x;
    const int wid  = tid >> 5;
    const int lane = tid & 31;

    const int start = g_seg_start[b];
    const int end   = g_seg_start[b + 1];
    const int n     = end - start;

    if (tid < EMB) dwf[tid] = w[tid * EMB + tid] * fingerprint[tid];
    __syncthreads();

    const float d0 = dwf[lane * 4 + 0];
    const float d1 = dwf[lane * 4 + 1];
    const float d2 = dwf[lane * 4 + 2];
    const float d3 = dwf[lane * 4 + 3];
    const float inv_scale = 0.08838834764831845f; // 1/sqrt(128)

    // Single pass: e_t = exp(score_t) is token-independent (max-shift dropped;
    // exact since scores are O(0.3)). Warp takes a token pair -> 4 independent
    // float4 loads in flight before the butterfly.
    float4 accV = make_float4(0.f, 0.f, 0.f, 0.f);
    float4 accK = make_float4(0.f, 0.f, 0.f, 0.f);
    float z = 0.f;

    const float* kbase = key   + (long long)start * EMB + lane * 4;
    const float* vbase = value + (long long)start * EMB + lane * 4;

    int t = wid * 2;
    for (; t + 1 < n; t += 16) {
        const float4 k0 = *reinterpret_cast<const float4*>(kbase + (long long)t * EMB);
        const float4 k1 = *reinterpret_cast<const float4*>(kbase + (long long)(t + 1) * EMB);
        const float4 v0 = *reinterpret_cast<const float4*>(vbase + (long long)t * EMB);
        const float4 v1 = *reinterpret_cast<const float4*>(vbase + (long long)(t + 1) * EMB);

        float p0 = (k0.x * d0 + k0.y * d1) + (k0.z * d2 + k0.w * d3);
        float p1 = (k1.x * d0 + k1.y * d1) + (k1.z * d2 + k1.w * d3);
        #pragma unroll
        for (int o = 16; o > 0; o >>= 1) {
            p0 += __shfl_xor_sync(0xffffffffu, p0, o);
            p1 += __shfl_xor_sync(0xffffffffu, p1, o);
        }
        const float e0 = __expf(p0 * inv_scale);
        const float e1 = __expf(p1 * inv_scale);
        z += e0 + e1;
        accK.x += e0 * k0.x + e1 * k1.x;
        accK.y += e0 * k0.y + e1 * k1.y;
        accK.z += e0 * k0.z + e1 * k1.z;
        accK.w += e0 * k0.w + e1 * k1.w;
        accV.x += e0 * v0.x + e1 * v1.x;
        accV.y += e0 * v0.y + e1 * v1.y;
        accV.z += e0 * v0.z + e1 * v1.z;
        accV.w += e0 * v0.w + e1 * v1.w;
    }
    if (t < n) {  // tail token
        const float4 k0 = *reinterpret_cast<const float4*>(kbase + (long long)t * EMB);
        const float4 v0 = *reinterpret_cast<const float4*>(vbase + (long long)t * EMB);
        float p0 = (k0.x * d0 + k0.y * d1) + (k0.z * d2 + k0.w * d3);
        #pragma unroll
        for (int o = 16; o > 0; o >>= 1) p0 += __shfl_xor_sync(0xffffffffu, p0, o);
        const float e0 = __expf(p0 * inv_scale);
        z += e0;
        accK.x += e0 * k0.x; accK.y += e0 * k0.y;
        accK.z += e0 * k0.z; accK.w += e0 * k0.w;
        accV.x += e0 * v0.x; accV.y += e0 * v0.y;
        accV.z += e0 * v0.z; accV.w += e0 * v0.w;
    }

    wsum[wid][lane]      = accV;   // value cols lane*4..+3
    wsum[wid][32 + lane] = accK;   // key   cols lane*4..+3
    if (lane == 0) zred[wid] = z;  // z identical across lanes (butterfly)
    __syncthreads();

    // Cross-warp reduce: thread c owns output column c.
    float zz = (zred[0] + zred[1]) + (zred[2] + zred[3])
             + (zred[4] + zred[5]) + (zred[6] + zred[7]);
    const float invZ = (zz > 0.f) ? (1.f / zz) : 0.f;

    const float* ws = reinterpret_cast<const float*>(wsum);  // [8][256]
    const float a0 = ws[0 * 256 + tid], a1 = ws[1 * 256 + tid];
    const float a2 = ws[2 * 256 + tid], a3 = ws[3 * 256 + tid];
    const float a4 = ws[4 * 256 + tid], a5 = ws[5 * 256 + tid];
    const float a6 = ws[6 * 256 + tid], a7 = ws[7 * 256 + tid];
    const float acc = ((a0 + a1) + (a2 + a3)) + ((a4 + a5) + (a6 + a7));
    out[(long long)b * (2 * EMB) + tid] = acc * invZ;
}

extern "C" void kernel_launch(void* const* d_in, const int* in_sizes, int n_in,
                              void* d_out, int out_size) {
    const float* value = (const float*)d_in[0];
    const float* key   = (const float*)d_in[1];
    const int*   seg   = (const int*)d_in[2];
    const float* fp    = (const float*)d_in[3];
    const float* w     = (const float*)d_in[4];
    float* out = (float*)d_out;
    const int T = in_sizes[2];

    const int nthreads_bounds = 256;
    const int nblocks_bounds = ((T + 3) / 4 + nthreads_bounds - 1) / nthreads_bounds;
    bounds_scan_kernel<<<nblocks_bounds, nthreads_bounds>>>(seg, T);
    fattn_kernel<<<BATCH, NTHREADS>>>(value, key, fp, w, out);
}

// round 13
// speedup vs baseline: 1.1404x; 1.0398x over previous
#include <cuda_runtime.h>
#include <math.h>

#define EMB 128
#define BATCH 8192
#define NTHREADS 256
#define FULLMASK 0xffffffffu

__device__ int g_seg_start[BATCH + 1];

// Vectorized boundary scan: thread i covers tokens 4i..4i+3 via one int4 load.
__global__ void bounds_scan_kernel(const int* __restrict__ seg, int T) {
    const int i = blockIdx.x * blockDim.x + threadIdx.x;
    const int base = i * 4;
    if (base >= T) return;

    if (base + 3 < T) {
        const int4 s4 = *reinterpret_cast<const int4*>(seg + base);
        int prev;
        if (base == 0) {
            for (int b = 0; b <= s4.x; b++) g_seg_start[b] = 0;
            prev = s4.x;
        } else {
            prev = seg[base - 1];
            for (int b = prev + 1; b <= s4.x; b++) g_seg_start[b] = base;
            prev = s4.x;
        }
        for (int b = prev + 1; b <= s4.y; b++) g_seg_start[b] = base + 1;
        for (int b = s4.y + 1; b <= s4.z; b++) g_seg_start[b] = base + 2;
        for (int b = s4.z + 1; b <= s4.w; b++) g_seg_start[b] = base + 3;
        if (base + 4 == T) {
            for (int b = s4.w + 1; b <= BATCH; b++) g_seg_start[b] = T;
        }
    } else {
        for (int j = base; j < T; j++) {
            const int s = seg[j];
            if (j == 0) {
                for (int b = 0; b <= s; b++) g_seg_start[b] = 0;
            } else {
                const int prev = seg[j - 1];
                for (int b = prev + 1; b <= s; b++) g_seg_start[b] = j;
            }
            if (j == T - 1) {
                for (int b = s + 1; b <= BATCH; b++) g_seg_start[b] = T;
            }
        }
    }
}

__global__ __launch_bounds__(NTHREADS, 6)
void fattn_kernel(const float* __restrict__ value,
                  const float* __restrict__ key,
                  const float* __restrict__ fingerprint,
                  const float* __restrict__ w,
                  float* __restrict__ out) {
    __shared__ float4 wsum[8][64];
    __shared__ float zred[8];
    __shared__ float dwf[EMB];

    const int b    = blockIdx.x;
    const int tid  = threadIdx.x;
    const int wid  = tid >> 5;
    const int lane = tid & 31;

    const int start = g_seg_start[b];
    const int end   = g_seg_start[b + 1];
    const int n     = end - start;

    if (tid < EMB) dwf[tid] = w[tid * EMB + tid] * fingerprint[tid];
    __syncthreads();

    const float d0 = dwf[lane * 4 + 0];
    const float d1 = dwf[lane * 4 + 1];
    const float d2 = dwf[lane * 4 + 2];
    const float d3 = dwf[lane * 4 + 3];
    const float inv_scale = 0.08838834764831845f; // 1/sqrt(128)
    const bool lo_half = (lane < 16);

    float4 accV = make_float4(0.f, 0.f, 0.f, 0.f);
    float4 accK = make_float4(0.f, 0.f, 0.f, 0.f);
    float z = 0.f;

    const float* kbase = key   + (long long)start * EMB + lane * 4;
    const float* vbase = value + (long long)start * EMB + lane * 4;

    int t = wid * 2;
    for (; t + 1 < n; t += 16) {
        const float4 k0 = *reinterpret_cast<const float4*>(kbase + (long long)t * EMB);
        const float4 k1 = *reinterpret_cast<const float4*>(kbase + (long long)(t + 1) * EMB);
        const float4 v0 = *reinterpret_cast<const float4*>(vbase + (long long)t * EMB);
        const float4 v1 = *reinterpret_cast<const float4*>(vbase + (long long)(t + 1) * EMB);

        float p0 = (k0.x * d0 + k0.y * d1) + (k0.z * d2 + k0.w * d3);
        float p1 = (k1.x * d0 + k1.y * d1) + (k1.z * d2 + k1.w * d3);
        // Split butterfly: one cross-half step on both, then each half
        // finishes one value; exchange the exps. 7 SHFL + 1 MUFU (was 10+2).
        p0 += __shfl_xor_sync(FULLMASK, p0, 16);
        p1 += __shfl_xor_sync(FULLMASK, p1, 16);
        float q = lo_half ? p0 : p1;
        #pragma unroll
        for (int o = 8; o > 0; o >>= 1) q += __shfl_xor_sync(FULLMASK, q, o);
        const float e  = __expf(q * inv_scale);
        const float eo = __shfl_xor_sync(FULLMASK, e, 16);
        const float e0 = lo_half ? e : eo;
        const float e1 = lo_half ? eo : e;

        z += e0 + e1;
        accK.x += e0 * k0.x + e1 * k1.x;
        accK.y += e0 * k0.y + e1 * k1.y;
        accK.z += e0 * k0.z + e1 * k1.z;
        accK.w += e0 * k0.w + e1 * k1.w;
        accV.x += e0 * v0.x + e1 * v1.x;
        accV.y += e0 * v0.y + e1 * v1.y;
        accV.z += e0 * v0.z + e1 * v1.z;
        accV.w += e0 * v0.w + e1 * v1.w;
    }
    if (t < n) {  // tail token: plain 5-step butterfly
        const float4 k0 = *reinterpret_cast<const float4*>(kbase + (long long)t * EMB);
        const float4 v0 = *reinterpret_cast<const float4*>(vbase + (long long)t * EMB);
        float p0 = (k0.x * d0 + k0.y * d1) + (k0.z * d2 + k0.w * d3);
        #pragma unroll
        for (int o = 16; o > 0; o >>= 1) p0 += __shfl_xor_sync(FULLMASK, p0, o);
        const float e0 = __expf(p0 * inv_scale);
        z += e0;
        accK.x += e0 * k0.x; accK.y += e0 * k0.y;
        accK.z += e0 * k0.z; accK.w += e0 * k0.w;
        accV.x += e0 * v0.x; accV.y += e0 * v0.y;
        accV.z += e0 * v0.z; accV.w += e0 * v0.w;
    }

    wsum[wid][lane]      = accV;   // value cols lane*4..+3
    wsum[wid][32 + lane] = accK;   // key   cols lane*4..+3
    if (lane == 0) zred[wid] = z;  // z identical across lanes
    __syncthreads();

    float zz = (zred[0] + zred[1]) + (zred[2] + zred[3])
             + (zred[4] + zred[5]) + (zred[6] + zred[7]);
    const float invZ = (zz > 0.f) ? (1.f / zz) : 0.f;

    const float* ws = reinterpret_cast<const float*>(wsum);  // [8][256]
    const float a0 = ws[0 * 256 + tid], a1 = ws[1 * 256 + tid];
    const float a2 = ws[2 * 256 + tid], a3 = ws[3 * 256 + tid];
    const float a4 = ws[4 * 256 + tid], a5 = ws[5 * 256 + tid];
    const float a6 = ws[6 * 256 + tid], a7 = ws[7 * 256 + tid];
    const float acc = ((a0 + a1) + (a2 + a3)) + ((a4 + a5) + (a6 + a7));
    out[(long long)b * (2 * EMB) + tid] = acc * invZ;
}

extern "C" void kernel_launch(void* const* d_in, const int* in_sizes, int n_in,
                              void* d_out, int out_size) {
    const float* value = (const float*)d_in[0];
    const float* key   = (const float*)d_in[1];
    const int*   seg   = (const int*)d_in[2];
    const float* fp    = (const float*)d_in[3];
    const float* w     = (const float*)d_in[4];
    float* out = (float*)d_out;
    const int T = in_sizes[2];

    const int nthreads_bounds = 256;
    const int nblocks_bounds = ((T + 3) / 4 + nthreads_bounds - 1) / nthreads_bounds;
    bounds_scan_kernel<<<nblocks_bounds, nthreads_bounds>>>(seg, T);
    fattn_kernel<<<BATCH, NTHREADS>>>(value, key, fp, w, out);
}